// round 1
// baseline (speedup 1.0000x reference)
#include <cuda_runtime.h>
#include <math.h>

#define FULLM 0xffffffffu
#define MINN 1e-15f
#define MAXNORM 0.996f   // (1 - 0.004) / sqrt(c), c = 1

// ---------------- device scratch (no allocations allowed) ----------------
__device__ float g_feats[4 * 1024 * 32];   // logmap0(in_feats)
__device__ float g_hb1[160];               // proj(expmap0(b1))
__device__ float g_hb2[32];                // proj(expmap0(b2))
__device__ float g_hbn2[2];                // |hb1|^2, |hb2|^2

// ---------------- helpers ----------------
__device__ __forceinline__ float wredsum(float v) {
#pragma unroll
    for (int o = 16; o; o >>= 1) v += __shfl_xor_sync(FULLM, v, o);
    return v;
}
__device__ __forceinline__ float artanhf_(float x) {
    x = fminf(fmaxf(x, -1.f + 1e-7f), 1.f - 1e-7f);
    return 0.5f * (log1pf(x) - log1pf(-x));
}
__device__ __forceinline__ float tanh15f_(float x) {
    return tanhf(fminf(fmaxf(x, -15.f), 15.f));
}

template <int J>
__device__ __forceinline__ float vnorm(const float* v) {
    float s = 0.f;
#pragma unroll
    for (int j = 0; j < J; j++) s += v[j] * v[j];
    return fmaxf(sqrtf(wredsum(s)), MINN);
}
template <int J>
__device__ __forceinline__ void projv(float* v) {
    float n = vnorm<J>(v);
    if (n > MAXNORM) {
        float f = MAXNORM / n;
#pragma unroll
        for (int j = 0; j < J; j++) v[j] *= f;
    }
}

// Full per-row pipeline. Input x: one component per lane (32-dim row).
// Output: 32*J-dim vector, lane holds components m = lane*J + j.
//   out = hnn_layer(to_hyp(x), W, b)            if !final_logmap
//   out = logmap0(hnn_layer(to_hyp(x), W, b))   if  final_logmap
// wt is W transposed in smem: wt[d*(32*J) + m] = W[m][d].
template <int J>
__device__ __forceinline__ void row_pipeline(float x, const float* wt, const float* hb,
                                             float hbn2, float* outp, bool final_logmap) {
    const int lane = threadIdx.x & 31;
    // to_hyp = proj(expmap0(x))
    float xn = fmaxf(sqrtf(wredsum(x * x)), MINN);
    float p = tanh15f_(xn) / xn * x;
    {
        float pn0 = fmaxf(sqrtf(wredsum(p * p)), MINN);
        if (pn0 > MAXNORM) p *= MAXNORM / pn0;
    }
    float pn = fmaxf(sqrtf(wredsum(p * p)), MINN);
    // mobius_matvec: mx = W @ p
    float mx[J];
#pragma unroll
    for (int j = 0; j < J; j++) mx[j] = 0.f;
#pragma unroll
    for (int d = 0; d < 32; d++) {
        float pd = __shfl_sync(FULLM, p, d);
#pragma unroll
        for (int j = 0; j < J; j++)
            mx[j] = fmaf(wt[d * (32 * J) + lane * J + j], pd, mx[j]);
    }
    float mxn = vnorm<J>(mx);
    float sc = tanh15f_(mxn / pn * artanhf_(pn)) / mxn;
    bool lz = false;
#pragma unroll
    for (int j = 0; j < J; j++) lz = lz || (mx[j] != 0.f);
    float zf = __ballot_sync(FULLM, lz) ? 1.f : 0.f;
    float res[J];
#pragma unroll
    for (int j = 0; j < J; j++) res[j] = zf * sc * mx[j];
    projv<J>(res);
    // mobius_add(res, hyp_bias), then proj
    float sx = 0.f, sxy = 0.f;
#pragma unroll
    for (int j = 0; j < J; j++) {
        float y = hb[lane * J + j];
        sx += res[j] * res[j];
        sxy += res[j] * y;
    }
    float x2 = wredsum(sx), xy = wredsum(sxy);
    float num_a = 1.f + 2.f * xy + hbn2;
    float num_b = 1.f - x2;
    float den = fmaxf(1.f + 2.f * xy + x2 * hbn2, MINN);
    float h[J];
#pragma unroll
    for (int j = 0; j < J; j++) h[j] = (num_a * res[j] + num_b * hb[lane * J + j]) / den;
    projv<J>(h);
    // xt = relu(logmap0(h))
    float hn = vnorm<J>(h);
    float th = artanhf_(hn) / hn;
    float xt[J];
#pragma unroll
    for (int j = 0; j < J; j++) xt[j] = fmaxf(th * h[j], 0.f);
    // o = proj(expmap0(xt))
    float tn = vnorm<J>(xt);
    float se = tanh15f_(tn) / tn;
    float o[J];
#pragma unroll
    for (int j = 0; j < J; j++) o[j] = se * xt[j];
    projv<J>(o);
    if (final_logmap) {
        float on = vnorm<J>(o);
        float tl = artanhf_(on) / on;
#pragma unroll
        for (int j = 0; j < J; j++) outp[j] = tl * o[j];
    } else {
#pragma unroll
        for (int j = 0; j < J; j++) outp[j] = o[j];
    }
}

// ---------------- kernel 0: hyperbolic biases ----------------
__global__ void k_bias(const float* __restrict__ b1, const float* __restrict__ b2) {
    int wid = threadIdx.x >> 5, lane = threadIdx.x & 31;
    if (wid == 0) {
        float v[5];
        float s = 0.f;
#pragma unroll
        for (int j = 0; j < 5; j++) { v[j] = b1[lane * 5 + j]; s += v[j] * v[j]; }
        float n = fmaxf(sqrtf(wredsum(s)), MINN);
        float f = tanh15f_(n) / n;
#pragma unroll
        for (int j = 0; j < 5; j++) v[j] *= f;
        projv<5>(v);
        s = 0.f;
#pragma unroll
        for (int j = 0; j < 5; j++) s += v[j] * v[j];
        float n2 = wredsum(s);
#pragma unroll
        for (int j = 0; j < 5; j++) g_hb1[lane * 5 + j] = v[j];
        if (lane == 0) g_hbn2[0] = n2;
    } else if (wid == 1) {
        float v[1];
        v[0] = b2[lane];
        float n = fmaxf(sqrtf(wredsum(v[0] * v[0])), MINN);
        v[0] *= tanh15f_(n) / n;
        projv<1>(v);
        float n2 = wredsum(v[0] * v[0]);
        g_hb2[lane] = v[0];
        if (lane == 0) g_hbn2[1] = n2;
    }
}

// ---------------- kernel 1: feats_t = logmap0(in_feats) ----------------
__global__ void __launch_bounds__(256) k_feats(const float* __restrict__ inf_) {
    int wid = threadIdx.x >> 5, lane = threadIdx.x & 31;
    int row = blockIdx.x * 8 + wid;   // 4096 rows, grid = 512
    float x = inf_[row * 32 + lane];
    float n = fmaxf(sqrtf(wredsum(x * x)), MINN);
    g_feats[row * 32 + lane] = artanhf_(n) / n * x;
}

// ---------------- kernel 2: fused gather + hyperbolic attention ----------------
__global__ void __launch_bounds__(192) k_main(const float* __restrict__ in_nei,
                                              const float* __restrict__ W1,
                                              const float* __restrict__ W2,
                                              float* __restrict__ outp,
                                              float* __restrict__ attr) {
    __shared__ float w1t[32 * 160];
    __shared__ float w2t[32 * 32];
    __shared__ float hb1[160];
    __shared__ float hb2[32];
    __shared__ float hbn2s[2];
    __shared__ float gbuf[6][160];   // rows 0..4 = neighbor heads, row 5 = agent
    __shared__ float attb[32];
    __shared__ float attp[32];

    const int tid = threadIdx.x;
    const int bid = blockIdx.x;      // b*1024 + a
    for (int i = tid; i < 5120; i += 192) { int m = i >> 5, d = i & 31; w1t[d * 160 + m] = W1[i]; }
    for (int i = tid; i < 1024; i += 192) { int m = i >> 5, d = i & 31; w2t[d * 32 + m] = W2[i]; }
    if (tid < 160) hb1[tid] = g_hb1[tid];
    if (tid >= 160 && tid < 192) hb2[tid - 160] = g_hb2[tid - 160];
    if (tid < 2) hbn2s[tid] = g_hbn2[tid];
    __syncthreads();

    const int wid = tid >> 5, lane = tid & 31;
    const int b = bid >> 10;

    float x;
    if (wid == 5) {
        // agent row
        x = g_feats[bid * 32 + lane];
    } else {
        // dense einsum over the (sparse one-hot) neighbor weights: warp wid -> k = wid
        const float4* nei4 = (const float4*)(in_nei + ((size_t)bid * 5 + wid) * 1024);
        const float* fb = g_feats + b * (1024 * 32);
        float acc = 0.f;
#pragma unroll
        for (int it = 0; it < 8; it++) {
            float4 w4 = nei4[it * 32 + lane];
            bool nz = (w4.x != 0.f) || (w4.y != 0.f) || (w4.z != 0.f) || (w4.w != 0.f);
            unsigned mk = __ballot_sync(FULLM, nz);
            while (mk) {
                int src = __ffs(mk) - 1;
                mk &= mk - 1u;
                float wx = __shfl_sync(FULLM, w4.x, src);
                float wy = __shfl_sync(FULLM, w4.y, src);
                float wz = __shfl_sync(FULLM, w4.z, src);
                float ww = __shfl_sync(FULLM, w4.w, src);
                int n0 = (it * 32 + src) * 4;
                if (wx != 0.f) acc = fmaf(wx, fb[(n0 + 0) * 32 + lane], acc);
                if (wy != 0.f) acc = fmaf(wy, fb[(n0 + 1) * 32 + lane], acc);
                if (wz != 0.f) acc = fmaf(wz, fb[(n0 + 2) * 32 + lane], acc);
                if (ww != 0.f) acc = fmaf(ww, fb[(n0 + 3) * 32 + lane], acc);
            }
        }
        x = acc;
    }

    // heads: g = logmap0(hnn_layer(to_hyp(x), W1, b1))
    float g[5];
    row_pipeline<5>(x, w1t, hb1, hbn2s[0], g, true);
#pragma unroll
    for (int j = 0; j < 5; j++) gbuf[wid][lane * 5 + j] = g[j];
    __syncthreads();

    if (wid == 0) {
        // attention: att[h][k] = <agent_head_h, neigh_head_{k,h}>  (dim 32)
        const int hh = lane / 5, kk = lane - hh * 5;
        float a_un = 0.f;
        if (lane < 25) {
            float s = 0.f;
#pragma unroll
            for (int d = 0; d < 32; d++)
                s = fmaf(gbuf[5][d * 5 + hh], gbuf[kk][d * 5 + hh], s);
            a_un = s;
        }
        attb[lane] = a_un;
        __syncwarp();
        float aval = 0.f;
        if (lane < 25) {
            float m = -3.4e38f;
            for (int k2 = 0; k2 < 5; k2++) m = fmaxf(m, attb[hh * 5 + k2]);
            float se = 0.f;
            for (int k2 = 0; k2 < 5; k2++) se += expf(attb[hh * 5 + k2] - m);
            aval = expf(a_un - m) / se;
            attr[(size_t)bid * 25 + lane] = aval;
        }
        attp[lane] = aval;
        __syncwarp();
        // out[d] = mean_h sum_k att[h][k] * neigh_head[k][d*5+h]
        float o = 0.f;
#pragma unroll
        for (int h2 = 0; h2 < 5; h2++)
#pragma unroll
            for (int k2 = 0; k2 < 5; k2++)
                o = fmaf(attp[h2 * 5 + k2], gbuf[k2][lane * 5 + h2], o);
        o *= 0.2f;
        // final layer: hnn_layer(to_hyp(o), W2, b2)
        float ov[1];
        row_pipeline<1>(o, w2t, hb2, hbn2s[1], ov, false);
        outp[(size_t)bid * 32 + lane] = ov[0];
    }
}

extern "C" void kernel_launch(void* const* d_in, const int* in_sizes, int n_in,
                              void* d_out, int out_size) {
    const float* in_feats = (const float*)d_in[0];
    const float* in_nei   = (const float*)d_in[1];
    const float* W1       = (const float*)d_in[2];
    const float* b1       = (const float*)d_in[3];
    const float* W2       = (const float*)d_in[4];
    const float* b2       = (const float*)d_in[5];
    float* outp = (float*)d_out;
    float* attr = outp + 4 * 1024 * 32;   // out first, att_record second

    k_bias<<<1, 64>>>(b1, b2);
    k_feats<<<512, 256>>>(in_feats);
    k_main<<<4096, 192>>>(in_nei, W1, W2, outp, attr);
}

// round 3
// speedup vs baseline: 2.1774x; 2.1774x over previous
#include <cuda_runtime.h>
#include <math.h>

#define FULLM 0xffffffffu
#define MINN 1e-15f
#define MAXNORM 0.996f   // (1 - 0.004) / sqrt(c), c = 1

// ---------------- device scratch ----------------
__device__ float g_feats[4 * 1024 * 32];        // logmap0(in_feats)
__device__ float g_heads[4096 * 6 * 160];       // head vectors, [h*32+d] layout (15.7MB, L2-resident)

// ---------------- helpers ----------------
__device__ __forceinline__ float wredsum(float v) {
#pragma unroll
    for (int o = 16; o; o >>= 1) v += __shfl_xor_sync(FULLM, v, o);
    return v;
}
__device__ __forceinline__ float artanhf_(float x) {
    x = fminf(fmaxf(x, -1.f + 1e-7f), 1.f - 1e-7f);
    return 0.5f * (log1pf(x) - log1pf(-x));
}
__device__ __forceinline__ float tanh15f_(float x) {
    return tanhf(fminf(fmaxf(x, -15.f), 15.f));
}

template <int J>
__device__ __forceinline__ float vnorm(const float* v) {
    float s = 0.f;
#pragma unroll
    for (int j = 0; j < J; j++) s += v[j] * v[j];
    return fmaxf(sqrtf(wredsum(s)), MINN);
}
template <int J>
__device__ __forceinline__ void projv(float* v) {
    float n = vnorm<J>(v);
    if (n > MAXNORM) {
        float f = MAXNORM / n;
#pragma unroll
        for (int j = 0; j < J; j++) v[j] *= f;
    }
}

// Compute hyp bias proj(expmap0(b)) for a J*32-dim vector; warp-collective.
template <int J>
__device__ __forceinline__ void make_hyp_bias(const float* b, float* hb, float* hbn2) {
    const int lane = threadIdx.x & 31;
    float v[J];
    float s = 0.f;
#pragma unroll
    for (int j = 0; j < J; j++) { v[j] = b[lane * J + j]; s += v[j] * v[j]; }
    float n = fmaxf(sqrtf(wredsum(s)), MINN);
    float f = tanh15f_(n) / n;
#pragma unroll
    for (int j = 0; j < J; j++) v[j] *= f;
    projv<J>(v);
    s = 0.f;
#pragma unroll
    for (int j = 0; j < J; j++) s += v[j] * v[j];
    float n2 = wredsum(s);
#pragma unroll
    for (int j = 0; j < J; j++) hb[lane * J + j] = v[j];
    if (lane == 0) *hbn2 = n2;
}

// Full per-row pipeline. Input x: one component per lane (32-dim row).
// Output: 32*J-dim vector, lane holds components m = lane*J + j.
// wt: W transposed in smem with row stride wstride: wt[d*wstride + m] = W[m][d].
template <int J>
__device__ __forceinline__ void row_pipeline(float x, const float* wt, int wstride,
                                             const float* hb, float hbn2,
                                             float* outp, bool final_logmap) {
    const int lane = threadIdx.x & 31;
    // to_hyp = proj(expmap0(x))
    float xn = fmaxf(sqrtf(wredsum(x * x)), MINN);
    float p = tanh15f_(xn) / xn * x;
    {
        float pn0 = fmaxf(sqrtf(wredsum(p * p)), MINN);
        if (pn0 > MAXNORM) p *= MAXNORM / pn0;
    }
    float pn = fmaxf(sqrtf(wredsum(p * p)), MINN);
    // mobius_matvec: mx = W @ p
    float mx[J];
#pragma unroll
    for (int j = 0; j < J; j++) mx[j] = 0.f;
#pragma unroll
    for (int d = 0; d < 32; d++) {
        float pd = __shfl_sync(FULLM, p, d);
#pragma unroll
        for (int j = 0; j < J; j++)
            mx[j] = fmaf(wt[d * wstride + lane * J + j], pd, mx[j]);
    }
    float mxn = vnorm<J>(mx);
    float sc = tanh15f_(mxn / pn * artanhf_(pn)) / mxn;
    bool lz = false;
#pragma unroll
    for (int j = 0; j < J; j++) lz = lz || (mx[j] != 0.f);
    float zf = __ballot_sync(FULLM, lz) ? 1.f : 0.f;
    float res[J];
#pragma unroll
    for (int j = 0; j < J; j++) res[j] = zf * sc * mx[j];
    projv<J>(res);
    // mobius_add(res, hyp_bias), then proj
    float sx = 0.f, sxy = 0.f;
#pragma unroll
    for (int j = 0; j < J; j++) {
        float y = hb[lane * J + j];
        sx += res[j] * res[j];
        sxy += res[j] * y;
    }
    float x2 = wredsum(sx), xy = wredsum(sxy);
    float num_a = 1.f + 2.f * xy + hbn2;
    float num_b = 1.f - x2;
    float den = fmaxf(1.f + 2.f * xy + x2 * hbn2, MINN);
    float h[J];
#pragma unroll
    for (int j = 0; j < J; j++) h[j] = (num_a * res[j] + num_b * hb[lane * J + j]) / den;
    projv<J>(h);
    // xt = relu(logmap0(h))
    float hn = vnorm<J>(h);
    float th = artanhf_(hn) / hn;
    float xt[J];
#pragma unroll
    for (int j = 0; j < J; j++) xt[j] = fmaxf(th * h[j], 0.f);
    // o = proj(expmap0(xt))
    float tn = vnorm<J>(xt);
    float se = tanh15f_(tn) / tn;
    float o[J];
#pragma unroll
    for (int j = 0; j < J; j++) o[j] = se * xt[j];
    projv<J>(o);
    if (final_logmap) {
        float on = vnorm<J>(o);
        float tl = artanhf_(on) / on;
#pragma unroll
        for (int j = 0; j < J; j++) outp[j] = tl * o[j];
    } else {
#pragma unroll
        for (int j = 0; j < J; j++) outp[j] = o[j];
    }
}

// ---------------- kernel 0: feats_t = logmap0(in_feats) ----------------
__global__ void __launch_bounds__(256) k_feats(const float* __restrict__ inf_) {
    int wid = threadIdx.x >> 5, lane = threadIdx.x & 31;
    int row = blockIdx.x * 8 + wid;   // 4096 rows, grid = 512
    float x = inf_[row * 32 + lane];
    float n = fmaxf(sqrtf(wredsum(x * x)), MINN);
    g_feats[row * 32 + lane] = artanhf_(n) / n * x;
}

// ---------------- kernel 1: gather + W1 head pipeline, one warp per row ----------------
// tasks t in [0, 24576): bid = t/6, k = t%6 (k==5 -> agent row).
// block = 256 (8 warps), each warp does 4 tasks -> 32 tasks/block, grid = 768.
// Next task's one-hot row is prefetched before the current task's ALU pipeline.
__global__ void __launch_bounds__(256) k_heads(const float* __restrict__ in_nei,
                                               const float* __restrict__ W1,
                                               const float* __restrict__ b1) {
    __shared__ float w1t[32 * 161];   // [d*161 + m], padded: conflict-free
    __shared__ float hb1[160];
    __shared__ float shbn2;

    const int tid = threadIdx.x;
    const int wid = tid >> 5, lane = tid & 31;

    if (wid == 0) {
        make_hyp_bias<5>(b1, hb1, &shbn2);
    } else {
        for (int i = tid - 32; i < 5120; i += 224) {
            int m = i >> 5, d = i & 31;
            w1t[d * 161 + m] = W1[i];
        }
    }
    __syncthreads();

    const int base = blockIdx.x * 32 + wid * 4;

    // prefetch buffer for the one-hot tile of the "current" task
    float4 w4[8];
    {
        const int t0 = base;
        const int bid0 = t0 / 6, k0 = t0 - bid0 * 6;
        if (k0 != 5) {
            const float4* nei4 = (const float4*)(in_nei + ((size_t)bid0 * 5 + k0) * 1024);
#pragma unroll
            for (int it = 0; it < 8; it++) w4[it] = nei4[it * 32 + lane];
        }
    }

#pragma unroll 1
    for (int r = 0; r < 4; r++) {
        const int t = base + r;
        const int bid = t / 6;
        const int k = t - bid * 6;

        float x;
        if (k == 5) {
            x = g_feats[bid * 32 + lane];
        } else {
            const float* fb = g_feats + (bid >> 10) * (1024 * 32);
            float acc = 0.f;
#pragma unroll
            for (int it = 0; it < 8; it++) {
                bool nz = (w4[it].x != 0.f) || (w4[it].y != 0.f) ||
                          (w4[it].z != 0.f) || (w4[it].w != 0.f);
                unsigned mk = __ballot_sync(FULLM, nz);
                while (mk) {
                    int src = __ffs(mk) - 1;
                    mk &= mk - 1u;
                    float wx = __shfl_sync(FULLM, w4[it].x, src);
                    float wy = __shfl_sync(FULLM, w4[it].y, src);
                    float wz = __shfl_sync(FULLM, w4[it].z, src);
                    float ww = __shfl_sync(FULLM, w4[it].w, src);
                    int n0 = (it * 32 + src) * 4;
                    if (wx != 0.f) acc = fmaf(wx, fb[(n0 + 0) * 32 + lane], acc);
                    if (wy != 0.f) acc = fmaf(wy, fb[(n0 + 1) * 32 + lane], acc);
                    if (wz != 0.f) acc = fmaf(wz, fb[(n0 + 2) * 32 + lane], acc);
                    if (ww != 0.f) acc = fmaf(ww, fb[(n0 + 3) * 32 + lane], acc);
                }
            }
            x = acc;
        }

        // prefetch next task's one-hot tile so its DRAM latency overlaps this
        // task's transcendental pipeline
        if (r < 3) {
            const int tn_ = t + 1;
            const int bidn = tn_ / 6, kn = tn_ - bidn * 6;
            if (kn != 5) {
                const float4* nei4 = (const float4*)(in_nei + ((size_t)bidn * 5 + kn) * 1024);
#pragma unroll
                for (int it = 0; it < 8; it++) w4[it] = nei4[it * 32 + lane];
            }
        }

        float g[5];   // g[j] = head component (d=lane, h=j)
        row_pipeline<5>(x, w1t, 161, hb1, shbn2, g, true);
        // store in [h*32 + d] layout -> coalesced 128B stores
        float* gp = g_heads + (size_t)t * 160;
#pragma unroll
        for (int j = 0; j < 5; j++) gp[j * 32 + lane] = g[j];
    }
}

// ---------------- kernel 2: attention + final W2 layer, one warp per bid ----------------
__global__ void __launch_bounds__(256) k_att(const float* __restrict__ W2,
                                             const float* __restrict__ b2,
                                             float* __restrict__ outp,
                                             float* __restrict__ attr) {
    __shared__ float w2t[32 * 33];    // [d*33 + m], padded
    __shared__ float hb2[32];
    __shared__ float shbn2;
    __shared__ float gs[8][6 * 168];  // per-warp head slab, [k*168 + h*33 + d]
    __shared__ float attw[8][32];

    const int tid = threadIdx.x;
    const int wid = tid >> 5, lane = tid & 31;

    if (wid == 0) {
        make_hyp_bias<1>(b2, hb2, &shbn2);
    } else {
        for (int i = tid - 32; i < 1024; i += 224) {
            int m = i >> 5, d = i & 31;
            w2t[d * 33 + m] = W2[i];
        }
    }
    __syncthreads();

    const int bid = blockIdx.x * 8 + wid;
    // stage 6x160 head block into padded smem (coalesced L2 reads)
    const float* gp = g_heads + (size_t)bid * 6 * 160;
    float* myslab = gs[wid];
    for (int e = lane; e < 960; e += 32) {
        int k = e / 160;
        int rem = e - k * 160;
        int h = rem >> 5, d = rem & 31;
        myslab[k * 168 + h * 33 + d] = gp[e];
    }
    __syncwarp();

    // attention logits: lane -> (hh = lane/5, kk = lane%5), dot over d (32)
    const int hh = lane / 5, kk = lane - hh * 5;
    float a_un = 0.f;
    if (lane < 25) {
        const float* ag = myslab + 5 * 168 + hh * 33;
        const float* ng = myslab + kk * 168 + hh * 33;
        float s = 0.f;
#pragma unroll
        for (int d = 0; d < 32; d++) s = fmaf(ag[d], ng[d], s);
        a_un = s;
    }
    attw[wid][lane] = a_un;
    __syncwarp();
    float aval = 0.f;
    if (lane < 25) {
        float m = -3.4e38f;
#pragma unroll
        for (int k2 = 0; k2 < 5; k2++) m = fmaxf(m, attw[wid][hh * 5 + k2]);
        float se = 0.f;
#pragma unroll
        for (int k2 = 0; k2 < 5; k2++) se += __expf(attw[wid][hh * 5 + k2] - m);
        aval = __expf(a_un - m) / se;
        attr[(size_t)bid * 25 + lane] = aval;
    }
    attw[wid][lane] = aval;
    __syncwarp();

    // out[d=lane] = 0.2 * sum_{h,k} att[h][k] * neigh[k][h][d]
    float o = 0.f;
#pragma unroll
    for (int h2 = 0; h2 < 5; h2++)
#pragma unroll
        for (int k2 = 0; k2 < 5; k2++)
            o = fmaf(attw[wid][h2 * 5 + k2], myslab[k2 * 168 + h2 * 33 + lane], o);
    o *= 0.2f;

    float ov[1];
    row_pipeline<1>(o, w2t, 33, hb2, shbn2, ov, false);
    outp[(size_t)bid * 32 + lane] = ov[0];
}

extern "C" void kernel_launch(void* const* d_in, const int* in_sizes, int n_in,
                              void* d_out, int out_size) {
    const float* in_feats = (const float*)d_in[0];
    const float* in_nei   = (const float*)d_in[1];
    const float* W1       = (const float*)d_in[2];
    const float* b1       = (const float*)d_in[3];
    const float* W2       = (const float*)d_in[4];
    const float* b2       = (const float*)d_in[5];
    float* outp = (float*)d_out;
    float* attr = outp + 4 * 1024 * 32;   // out first, att_record second

    k_feats<<<512, 256>>>(in_feats);
    k_heads<<<768, 256>>>(in_nei, W1, b1);
    k_att<<<512, 256>>>(W2, b2, outp, attr);
}

// round 4
// speedup vs baseline: 2.5657x; 1.1783x over previous
#include <cuda_runtime.h>
#include <math.h>

#define FULLM 0xffffffffu
#define MINN 1e-15f
#define MAXNORM 0.996f   // (1 - 0.004) / sqrt(c), c = 1

// ---------------- device scratch ----------------
__device__ float g_feats[4 * 1024 * 32];        // logmap0(in_feats)
__device__ float g_heads[4096 * 6 * 160];       // head vectors, [h*32+d] layout

// ---------------- helpers ----------------
__device__ __forceinline__ float wredsum(float v) {
#pragma unroll
    for (int o = 16; o; o >>= 1) v += __shfl_xor_sync(FULLM, v, o);
    return v;
}
// fast tanh for x >= 0, clipped at 15 (matches tanh15 on nonneg args)
__device__ __forceinline__ float tanh_fast(float x) {
    x = fminf(x, 15.f);
    float e = __expf(-2.f * x);
    return __fdividef(1.f - e, 1.f + e);
}
// fast artanh with the reference clamp
__device__ __forceinline__ float artanh_fast(float x) {
    x = fminf(fmaxf(x, -1.f + 1e-7f), 1.f - 1e-7f);
    return 0.5f * __logf(__fdividef(1.f + x, 1.f - x));
}
// from s = sum of squares: n = max(sqrt(s), MINN), inv = 1/n
__device__ __forceinline__ void norm_inv(float s, float& n, float& inv) {
    s = fmaxf(s, 1e-30f);
    inv = __frsqrt_rn(s);
    n = s * inv;
}

// Hyp bias proj(expmap0(b)) for a J*32-dim vector; warp-collective, writes smem.
template <int J>
__device__ __forceinline__ void make_hyp_bias(const float* b, float* hb, float* hbn2) {
    const int lane = threadIdx.x & 31;
    float v[J];
    float s = 0.f;
#pragma unroll
    for (int j = 0; j < J; j++) { v[j] = b[lane * J + j]; s += v[j] * v[j]; }
    float n, inv;
    norm_inv(wredsum(s), n, inv);
    float t = tanh_fast(n);
#pragma unroll
    for (int j = 0; j < J; j++) v[j] *= t * inv;
    // |v| = t analytically; proj
    float f = (t > MAXNORM) ? __fdividef(MAXNORM, t) : 1.f;
    float vn = fminf(t, MAXNORM);
#pragma unroll
    for (int j = 0; j < J; j++) hb[lane * J + j] = v[j] * f;
    if (lane == 0) *hbn2 = vn * vn;
}

// ---- batched head pipeline: R rows at once, J = 5 heads ----
// x[r]: input component (dim = lane). g[r][j] = logmap0(hnn_layer(to_hyp(x)))
// component m = lane*5+j... stored later as [h][d] = [j][lane].
// wt: W1 transposed in smem, wt[d*161 + lane*5 + j] = W1[lane*5+j][d].
template <int R>
__device__ __forceinline__ void head_pipeline(const float* x, const float* wt,
                                              const float* hb, float hbn2,
                                              float g[][5]) {
    const int lane = threadIdx.x & 31;
    float hbl[5];
#pragma unroll
    for (int j = 0; j < 5; j++) hbl[j] = hb[lane * 5 + j];

    float p[R], pn[R];
#pragma unroll
    for (int r = 0; r < R; r++) {
        float n, inv;
        norm_inv(wredsum(x[r] * x[r]), n, inv);
        float t = tanh_fast(n);                       // |expmap0(x)| = tanh(|x|)
        float f = (t > MAXNORM) ? __fdividef(MAXNORM, t) : 1.f;
        p[r] = t * inv * x[r] * f;
        pn[r] = fminf(t, MAXNORM);
    }
    // matvec: mx[r][j] = sum_d W[lane*5+j][d] * p[r][d]
    float mx[R][5];
#pragma unroll
    for (int r = 0; r < R; r++)
#pragma unroll
        for (int j = 0; j < 5; j++) mx[r][j] = 0.f;
#pragma unroll
    for (int d = 0; d < 32; d++) {
        float w0 = wt[d * 161 + lane * 5 + 0];
        float w1 = wt[d * 161 + lane * 5 + 1];
        float w2 = wt[d * 161 + lane * 5 + 2];
        float w3 = wt[d * 161 + lane * 5 + 3];
        float w4 = wt[d * 161 + lane * 5 + 4];
#pragma unroll
        for (int r = 0; r < R; r++) {
            float pd = __shfl_sync(FULLM, p[r], d);
            mx[r][0] = fmaf(w0, pd, mx[r][0]);
            mx[r][1] = fmaf(w1, pd, mx[r][1]);
            mx[r][2] = fmaf(w2, pd, mx[r][2]);
            mx[r][3] = fmaf(w3, pd, mx[r][3]);
            mx[r][4] = fmaf(w4, pd, mx[r][4]);
        }
    }
#pragma unroll
    for (int r = 0; r < R; r++) {
        float s2 = 0.f;
#pragma unroll
        for (int j = 0; j < 5; j++) s2 += mx[r][j] * mx[r][j];
        float mxn, inv2;
        norm_inv(wredsum(s2), mxn, inv2);
        float arg = mxn * __fdividef(artanh_fast(pn[r]), pn[r]);
        float t2 = tanh_fast(arg);
        bool lz = (mx[r][0] != 0.f) || (mx[r][1] != 0.f) || (mx[r][2] != 0.f) ||
                  (mx[r][3] != 0.f) || (mx[r][4] != 0.f);
        float zf = __ballot_sync(FULLM, lz) ? 1.f : 0.f;
        float rn = zf * t2;                           // |res| pre-proj
        float fpr = (rn > MAXNORM) ? __fdividef(MAXNORM, rn) : 1.f;
        float sc = zf * t2 * inv2 * fpr;
        float res[5];
        float sxy = 0.f;
#pragma unroll
        for (int j = 0; j < 5; j++) {
            res[j] = sc * mx[r][j];
            sxy += res[j] * hbl[j];
        }
        float rp = fminf(rn, MAXNORM);
        float x2 = rp * rp;
        float xy = wredsum(sxy);
        float num_a = 1.f + 2.f * xy + hbn2;
        float num_b = 1.f - x2;
        float rden = __fdividef(1.f, fmaxf(1.f + 2.f * xy + x2 * hbn2, MINN));
        float h[5];
        float s3 = 0.f;
#pragma unroll
        for (int j = 0; j < 5; j++) {
            h[j] = (num_a * res[j] + num_b * hbl[j]) * rden;
            s3 += h[j] * h[j];
        }
        float hn, inv3;
        norm_inv(wredsum(s3), hn, inv3);
        float fh = (hn > MAXNORM) ? __fdividef(MAXNORM, hn) : 1.f;
        hn = fminf(hn, MAXNORM);
        float th = __fdividef(artanh_fast(hn), hn) * fh;
        float xt[5];
        float s4 = 0.f;
#pragma unroll
        for (int j = 0; j < 5; j++) {
            xt[j] = fmaxf(th * h[j], 0.f);
            s4 += xt[j] * xt[j];
        }
        float tn, inv4;
        norm_inv(wredsum(s4), tn, inv4);
        float t4 = tanh_fast(tn);                     // |expmap0(xt)|
        float fo = (t4 > MAXNORM) ? __fdividef(MAXNORM, t4) : 1.f;
        float on = fminf(t4, MAXNORM);
        float tl = __fdividef(artanh_fast(on), on);   // final logmap0 scale
        float oc = t4 * inv4 * fo * tl;
#pragma unroll
        for (int j = 0; j < 5; j++) g[r][j] = oc * xt[j];
    }
}

// ---- scalar pipeline for the final W2 layer (J = 1, no final logmap) ----
// wt[d*33 + lane] = W2[lane][d].
__device__ __forceinline__ float row_pipeline1(float x, const float* wt,
                                               float hbl, float hbn2) {
    const int lane = threadIdx.x & 31;
    float n, inv;
    norm_inv(wredsum(x * x), n, inv);
    float t = tanh_fast(n);
    float f = (t > MAXNORM) ? __fdividef(MAXNORM, t) : 1.f;
    float p = t * inv * x * f;
    float pn = fminf(t, MAXNORM);
    float mx = 0.f;
#pragma unroll
    for (int d = 0; d < 32; d++) {
        float pd = __shfl_sync(FULLM, p, d);
        mx = fmaf(wt[d * 33 + lane], pd, mx);
    }
    float mxn, inv2;
    norm_inv(wredsum(mx * mx), mxn, inv2);
    float arg = mxn * __fdividef(artanh_fast(pn), pn);
    float t2 = tanh_fast(arg);
    float zf = __ballot_sync(FULLM, mx != 0.f) ? 1.f : 0.f;
    float rn = zf * t2;
    float fpr = (rn > MAXNORM) ? __fdividef(MAXNORM, rn) : 1.f;
    float res = zf * t2 * inv2 * fpr * mx;
    float rp = fminf(rn, MAXNORM);
    float x2 = rp * rp;
    float xy = wredsum(res * hbl);
    float num_a = 1.f + 2.f * xy + hbn2;
    float num_b = 1.f - x2;
    float rden = __fdividef(1.f, fmaxf(1.f + 2.f * xy + x2 * hbn2, MINN));
    float h = (num_a * res + num_b * hbl) * rden;
    float hn, inv3;
    norm_inv(wredsum(h * h), hn, inv3);
    float fh = (hn > MAXNORM) ? __fdividef(MAXNORM, hn) : 1.f;
    hn = fminf(hn, MAXNORM);
    float th = __fdividef(artanh_fast(hn), hn) * fh;
    float xt = fmaxf(th * h, 0.f);
    float tn, inv4;
    norm_inv(wredsum(xt * xt), tn, inv4);
    float t4 = tanh_fast(tn);
    float fo = (t4 > MAXNORM) ? __fdividef(MAXNORM, t4) : 1.f;
    return t4 * inv4 * fo * xt;
}

// ---------------- kernel 0: feats_t = logmap0(in_feats) ----------------
__global__ void __launch_bounds__(256) k_feats(const float* __restrict__ inf_) {
    int wid = threadIdx.x >> 5, lane = threadIdx.x & 31;
    int row = blockIdx.x * 8 + wid;   // 4096 rows, grid = 512
    float x = inf_[row * 32 + lane];
    float n, inv;
    norm_inv(wredsum(x * x), n, inv);
    g_feats[row * 32 + lane] = __fdividef(artanh_fast(n), n) * x;
}

// ---------------- gather helpers ----------------
__device__ __forceinline__ void nei_load(float4 (&w)[8], const float* __restrict__ in_nei,
                                         size_t row, int lane) {
    const float4* p = (const float4*)(in_nei + row * 1024);
#pragma unroll
    for (int it = 0; it < 8; it++) w[it] = p[it * 32 + lane];
}
__device__ __forceinline__ float nei_consume(float4 (&w)[8], const float* __restrict__ fb,
                                             int lane) {
    float acc = 0.f;
#pragma unroll
    for (int it = 0; it < 8; it++) {
        bool nz = (w[it].x != 0.f) || (w[it].y != 0.f) || (w[it].z != 0.f) || (w[it].w != 0.f);
        unsigned mk = __ballot_sync(FULLM, nz);
        while (mk) {
            int src = __ffs(mk) - 1;
            mk &= mk - 1u;
            float wx = __shfl_sync(FULLM, w[it].x, src);
            float wy = __shfl_sync(FULLM, w[it].y, src);
            float wz = __shfl_sync(FULLM, w[it].z, src);
            float ww = __shfl_sync(FULLM, w[it].w, src);
            int n0 = (it * 32 + src) * 4;
            if (wx != 0.f) acc = fmaf(wx, fb[(n0 + 0) * 32 + lane], acc);
            if (wy != 0.f) acc = fmaf(wy, fb[(n0 + 1) * 32 + lane], acc);
            if (wz != 0.f) acc = fmaf(wz, fb[(n0 + 2) * 32 + lane], acc);
            if (ww != 0.f) acc = fmaf(ww, fb[(n0 + 3) * 32 + lane], acc);
        }
    }
    return acc;
}

// ---------------- kernel 1: gather + W1 head pipeline ----------------
// 24576 tasks, 4 per warp (SoA-batched), 8 warps/block, grid = 768.
__global__ void __launch_bounds__(256, 2) k_heads(const float* __restrict__ in_nei,
                                                  const float* __restrict__ W1,
                                                  const float* __restrict__ b1) {
    __shared__ float w1t[32 * 161];   // [d*161 + m], padded: conflict-free
    __shared__ float hb1[160];
    __shared__ float shbn2;

    const int tid = threadIdx.x;
    const int wid = tid >> 5, lane = tid & 31;

    if (wid == 0) {
        make_hyp_bias<5>(b1, hb1, &shbn2);
    } else {
        for (int i = tid - 32; i < 5120; i += 224) {
            int m = i >> 5, d = i & 31;
            w1t[d * 161 + m] = W1[i];
        }
    }
    __syncthreads();

    const int base = blockIdx.x * 32 + wid * 4;
    int bidv[4], kv[4];
#pragma unroll
    for (int r = 0; r < 4; r++) {
        int t = base + r;
        bidv[r] = t / 6;
        kv[r] = t - bidv[r] * 6;
    }
    const float* fb0 = g_feats + (bidv[0] >> 10) * (1024 * 32);
    const float* fb3 = g_feats + (bidv[3] >> 10) * (1024 * 32);

    // ping-pong double-buffered gather (at most one agent row among 4 tasks)
    float4 A[8], B[8];
    float x[4];
    if (kv[0] != 5) nei_load(A, in_nei, (size_t)bidv[0] * 5 + kv[0], lane);
    if (kv[1] != 5) nei_load(B, in_nei, (size_t)bidv[1] * 5 + kv[1], lane);
    x[0] = (kv[0] == 5) ? g_feats[bidv[0] * 32 + lane] : nei_consume(A, fb0, lane);
    if (kv[2] != 5) nei_load(A, in_nei, (size_t)bidv[2] * 5 + kv[2], lane);
    x[1] = (kv[1] == 5) ? g_feats[bidv[1] * 32 + lane] : nei_consume(B, fb0, lane);
    if (kv[3] != 5) nei_load(B, in_nei, (size_t)bidv[3] * 5 + kv[3], lane);
    x[2] = (kv[2] == 5) ? g_feats[bidv[2] * 32 + lane] : nei_consume(A, fb3, lane);
    x[3] = (kv[3] == 5) ? g_feats[bidv[3] * 32 + lane] : nei_consume(B, fb3, lane);

    float g[4][5];
    head_pipeline<4>(x, w1t, hb1, shbn2, g);

#pragma unroll
    for (int r = 0; r < 4; r++) {
        float* gp = g_heads + (size_t)(base + r) * 160;
#pragma unroll
        for (int j = 0; j < 5; j++) gp[j * 32 + lane] = g[r][j];
    }
}

// ---------------- kernel 2: attention + final W2 layer, one warp per bid ----------------
__global__ void __launch_bounds__(256) k_att(const float* __restrict__ W2,
                                             const float* __restrict__ b2,
                                             float* __restrict__ outp,
                                             float* __restrict__ attr) {
    __shared__ float w2t[32 * 33];    // [d*33 + m], padded
    __shared__ float hb2[32];
    __shared__ float shbn2;
    __shared__ float gs[8][6 * 168];  // per-warp head slab, [k*168 + h*33 + d]
    __shared__ float attw[8][32];

    const int tid = threadIdx.x;
    const int wid = tid >> 5, lane = tid & 31;

    if (wid == 0) {
        make_hyp_bias<1>(b2, hb2, &shbn2);
    } else {
        for (int i = tid - 32; i < 1024; i += 224) {
            int m = i >> 5, d = i & 31;
            w2t[d * 33 + m] = W2[i];
        }
    }
    __syncthreads();

    const int bid = blockIdx.x * 8 + wid;
    const float* gp = g_heads + (size_t)bid * 6 * 160;
    float* myslab = gs[wid];
    for (int e = lane; e < 960; e += 32) {
        int k = e / 160;
        int rem = e - k * 160;
        int h = rem >> 5, d = rem & 31;
        myslab[k * 168 + h * 33 + d] = gp[e];
    }
    __syncwarp();

    const int hh = lane / 5, kk = lane - hh * 5;
    float a_un = 0.f;
    if (lane < 25) {
        const float* ag = myslab + 5 * 168 + hh * 33;
        const float* ng = myslab + kk * 168 + hh * 33;
        float s = 0.f;
#pragma unroll
        for (int d = 0; d < 32; d++) s = fmaf(ag[d], ng[d], s);
        a_un = s;
    }
    attw[wid][lane] = a_un;
    __syncwarp();
    float aval = 0.f;
    if (lane < 25) {
        float m = -3.4e38f;
#pragma unroll
        for (int k2 = 0; k2 < 5; k2++) m = fmaxf(m, attw[wid][hh * 5 + k2]);
        float se = 0.f;
#pragma unroll
        for (int k2 = 0; k2 < 5; k2++) se += __expf(attw[wid][hh * 5 + k2] - m);
        aval = __expf(a_un - m) * __fdividef(1.f, se);
        attr[(size_t)bid * 25 + lane] = aval;
    }
    attw[wid][lane] = aval;
    __syncwarp();

    float o = 0.f;
#pragma unroll
    for (int h2 = 0; h2 < 5; h2++)
#pragma unroll
        for (int k2 = 0; k2 < 5; k2++)
            o = fmaf(attw[wid][h2 * 5 + k2], myslab[k2 * 168 + h2 * 33 + lane], o);
    o *= 0.2f;

    outp[(size_t)bid * 32 + lane] = row_pipeline1(o, w2t, hb2[lane], shbn2);
}

extern "C" void kernel_launch(void* const* d_in, const int* in_sizes, int n_in,
                              void* d_out, int out_size) {
    const float* in_feats = (const float*)d_in[0];
    const float* in_nei   = (const float*)d_in[1];
    const float* W1       = (const float*)d_in[2];
    const float* b1       = (const float*)d_in[3];
    const float* W2       = (const float*)d_in[4];
    const float* b2       = (const float*)d_in[5];
    float* outp = (float*)d_out;
    float* attr = outp + 4 * 1024 * 32;   // out first, att_record second

    k_feats<<<512, 256>>>(in_feats);
    k_heads<<<768, 256>>>(in_nei, W1, b1);
    k_att<<<512, 256>>>(W2, b2, outp, attr);
}

// round 5
// speedup vs baseline: 3.4126x; 1.3301x over previous
#include <cuda_runtime.h>
#include <math.h>

#define FULLM 0xffffffffu
#define MINN 1e-15f
#define MAXNORM 0.996f   // (1 - 0.004) / sqrt(c), c = 1

// ---------------- device scratch ----------------
__device__ float g_x[24576 * 32];   // gathered + logmapped input rows (3.1MB, L2-resident)

// ---------------- helpers ----------------
__device__ __forceinline__ float wredsum(float v) {
#pragma unroll
    for (int o = 16; o; o >>= 1) v += __shfl_xor_sync(FULLM, v, o);
    return v;
}
__device__ __forceinline__ float tanh_fast(float x) {   // x >= 0, clip 15
    x = fminf(x, 15.f);
    float e = __expf(-2.f * x);
    return __fdividef(1.f - e, 1.f + e);
}
__device__ __forceinline__ float artanh_fast(float x) {
    x = fminf(fmaxf(x, -1.f + 1e-7f), 1.f - 1e-7f);
    return 0.5f * __logf(__fdividef(1.f + x, 1.f - x));
}
__device__ __forceinline__ void norm_inv(float s, float& n, float& inv) {
    s = fmaxf(s, 1e-30f);
    inv = __frsqrt_rn(s);
    n = s * inv;
}

// hyp bias proj(expmap0(b)); warp-collective, writes smem
template <int J>
__device__ __forceinline__ void make_hyp_bias(const float* b, float* hb, float* hbn2) {
    const int lane = threadIdx.x & 31;
    float v[J];
    float s = 0.f;
#pragma unroll
    for (int j = 0; j < J; j++) { v[j] = b[lane * J + j]; s += v[j] * v[j]; }
    float n, inv;
    norm_inv(wredsum(s), n, inv);
    float t = tanh_fast(n);
#pragma unroll
    for (int j = 0; j < J; j++) v[j] *= t * inv;
    float f = (t > MAXNORM) ? __fdividef(MAXNORM, t) : 1.f;
    float vn = fminf(t, MAXNORM);
#pragma unroll
    for (int j = 0; j < J; j++) hb[lane * J + j] = v[j] * f;
    if (lane == 0) *hbn2 = vn * vn;
}

// ---------------- kernel 1: streaming gather + on-the-fly logmap ----------------
// tasks t in [0, 24576): bid = t/6, k = t%6 (k==5 -> agent row).
// One warp per task; lazy pair-granularity scan with early exit (one-hot rows).
__global__ void __launch_bounds__(256) k_gather(const float* __restrict__ in_nei,
                                                const float* __restrict__ in_feats) {
    const int tid = threadIdx.x, wid = tid >> 5, lane = tid & 31;
    const int t = blockIdx.x * 8 + wid;
    const int bid = t / 6;
    const int k = t - bid * 6;
    const float* fbase = in_feats + (bid >> 10) * (1024 * 32);

    float x = 0.f;
    if (k == 5) {
        float f = in_feats[bid * 32 + lane];
        float n, inv;
        norm_inv(wredsum(f * f), n, inv);
        x = __fdividef(artanh_fast(n), n) * f;
    } else {
        const float4* p = (const float4*)(in_nei + ((size_t)bid * 5 + k) * 1024);
        // accumulate one source component w at flat index n
        auto addc = [&](float w, int n) {
            if (w != 0.f) {   // warp-uniform (w is broadcast)
                float f = fbase[n * 32 + lane];
                float nn, inv;
                norm_inv(wredsum(f * f), nn, inv);
                x = fmaf(w * __fdividef(artanh_fast(nn), nn), f, x);
            }
        };
#pragma unroll 1
        for (int pr = 0; pr < 4; pr++) {
            float4 a = p[pr * 64 + lane];
            float4 b = p[pr * 64 + 32 + lane];
            bool nz = (a.x != 0.f) || (a.y != 0.f) || (a.z != 0.f) || (a.w != 0.f) ||
                      (b.x != 0.f) || (b.y != 0.f) || (b.z != 0.f) || (b.w != 0.f);
            unsigned mk = __ballot_sync(FULLM, nz);
            if (mk) {
                while (mk) {
                    int src = __ffs(mk) - 1;
                    mk &= mk - 1u;
                    float ax = __shfl_sync(FULLM, a.x, src), ay = __shfl_sync(FULLM, a.y, src);
                    float az = __shfl_sync(FULLM, a.z, src), aw = __shfl_sync(FULLM, a.w, src);
                    float bx = __shfl_sync(FULLM, b.x, src), by = __shfl_sync(FULLM, b.y, src);
                    float bz = __shfl_sync(FULLM, b.z, src), bw = __shfl_sync(FULLM, b.w, src);
                    int na = pr * 256 + src * 4;        // a half: it = pr*2
                    int nb = pr * 256 + 128 + src * 4;  // b half: it = pr*2+1
                    addc(ax, na + 0); addc(ay, na + 1); addc(az, na + 2); addc(aw, na + 3);
                    addc(bx, nb + 0); addc(by, nb + 1); addc(bz, nb + 2); addc(bw, nb + 3);
                }
                break;   // one-hot row: first nonzero pair is the only one
            }
        }
    }
    g_x[(size_t)t * 32 + lane] = x;
}

// ---------------- kernel 2: per-bid full pipeline (heads + attention + W2) ----------------
// one warp per bid; 8 warps/block; grid = 512. Dynamic smem.
__global__ void __launch_bounds__(256, 2) k_bidpipe(const float* __restrict__ W1,
                                                    const float* __restrict__ b1,
                                                    const float* __restrict__ W2,
                                                    const float* __restrict__ b2,
                                                    float* __restrict__ outp,
                                                    float* __restrict__ attr) {
    extern __shared__ float sm[];
    float* w1t = sm;                    // 32*161 = 5152  [d*161 + m]
    float* w2t = w1t + 5152;            // 32*33  = 1056  [d*33 + m]
    float* hb1 = w2t + 1056;            // 160
    float* hb2 = hb1 + 160;             // 32
    float* hbn = hb2 + 32;              // 2
    float* slab = hbn + 2;              // 8 * 1008  [wid][r*168 + j*33 + d]
    float* attws = slab + 8 * 1008;     // 8 * 32

    const int tid = threadIdx.x, wid = tid >> 5, lane = tid & 31;

    if (wid == 0) {
        make_hyp_bias<5>(b1, hb1, &hbn[0]);
    } else if (wid == 1) {
        make_hyp_bias<1>(b2, hb2, &hbn[1]);
    } else {
        for (int i = tid - 64; i < 6208; i += 192) {
            if (i < 5152) {
                int m = i >> 5, d = i & 31;
                w1t[d * 161 + m] = W1[i];
            } else {
                int j = i - 5152;
                int m = j >> 5, d = j & 31;
                w2t[d * 33 + m] = W2[j];
            }
        }
    }
    __syncthreads();

    const int bid = blockIdx.x * 8 + wid;
    const float hbn2 = hbn[0];
    float* myslab = slab + wid * 1008;

    float hbl[5];
#pragma unroll
    for (int j = 0; j < 5; j++) hbl[j] = hb1[lane * 5 + j];

    // ---- load 6 input rows and map to the ball ----
    float p[6], pn[6];
#pragma unroll
    for (int r = 0; r < 6; r++) {
        float xr = g_x[(size_t)(bid * 6 + r) * 32 + lane];
        float n, inv;
        norm_inv(wredsum(xr * xr), n, inv);
        float tt = tanh_fast(n);                      // |expmap0| = tanh(|x|)
        float f = (tt > MAXNORM) ? __fdividef(MAXNORM, tt) : 1.f;
        p[r] = tt * inv * xr * f;
        pn[r] = fminf(tt, MAXNORM);
    }
    // ---- batched matvec: mx[r][j] = sum_d W1[lane*5+j][d] * p[r][d] ----
    float mx[6][5];
#pragma unroll
    for (int r = 0; r < 6; r++)
#pragma unroll
        for (int j = 0; j < 5; j++) mx[r][j] = 0.f;
#pragma unroll
    for (int d = 0; d < 32; d++) {
        float w0 = w1t[d * 161 + lane * 5 + 0];
        float w1 = w1t[d * 161 + lane * 5 + 1];
        float w2 = w1t[d * 161 + lane * 5 + 2];
        float w3 = w1t[d * 161 + lane * 5 + 3];
        float w4 = w1t[d * 161 + lane * 5 + 4];
#pragma unroll
        for (int r = 0; r < 6; r++) {
            float pd = __shfl_sync(FULLM, p[r], d);
            mx[r][0] = fmaf(w0, pd, mx[r][0]);
            mx[r][1] = fmaf(w1, pd, mx[r][1]);
            mx[r][2] = fmaf(w2, pd, mx[r][2]);
            mx[r][3] = fmaf(w3, pd, mx[r][3]);
            mx[r][4] = fmaf(w4, pd, mx[r][4]);
        }
    }
    // ---- per-row epilogue, results straight into the smem slab ----
#pragma unroll
    for (int r = 0; r < 6; r++) {
        float s2 = 0.f;
#pragma unroll
        for (int j = 0; j < 5; j++) s2 += mx[r][j] * mx[r][j];
        float mxn, inv2;
        norm_inv(wredsum(s2), mxn, inv2);
        float arg = mxn * __fdividef(artanh_fast(pn[r]), pn[r]);
        float t2 = tanh_fast(arg);
        bool lz = (mx[r][0] != 0.f) || (mx[r][1] != 0.f) || (mx[r][2] != 0.f) ||
                  (mx[r][3] != 0.f) || (mx[r][4] != 0.f);
        float zf = __ballot_sync(FULLM, lz) ? 1.f : 0.f;
        float rn = zf * t2;
        float fpr = (rn > MAXNORM) ? __fdividef(MAXNORM, rn) : 1.f;
        float sc = zf * t2 * inv2 * fpr;
        float res[5];
        float sxy = 0.f;
#pragma unroll
        for (int j = 0; j < 5; j++) {
            res[j] = sc * mx[r][j];
            sxy += res[j] * hbl[j];
        }
        float rp = fminf(rn, MAXNORM);
        float x2 = rp * rp;
        float xy = wredsum(sxy);
        float num_a = 1.f + 2.f * xy + hbn2;
        float num_b = 1.f - x2;
        float rden = __fdividef(1.f, fmaxf(1.f + 2.f * xy + x2 * hbn2, MINN));
        float h[5];
        float s3 = 0.f;
#pragma unroll
        for (int j = 0; j < 5; j++) {
            h[j] = (num_a * res[j] + num_b * hbl[j]) * rden;
            s3 += h[j] * h[j];
        }
        float hn, inv3;
        norm_inv(wredsum(s3), hn, inv3);
        float fh = (hn > MAXNORM) ? __fdividef(MAXNORM, hn) : 1.f;
        hn = fminf(hn, MAXNORM);
        float th = __fdividef(artanh_fast(hn), hn) * fh;
        float xt[5];
        float s4 = 0.f;
#pragma unroll
        for (int j = 0; j < 5; j++) {
            xt[j] = fmaxf(th * h[j], 0.f);
            s4 += xt[j] * xt[j];
        }
        float tn, inv4;
        norm_inv(wredsum(s4), tn, inv4);
        float t4 = tanh_fast(tn);
        float fo = (t4 > MAXNORM) ? __fdividef(MAXNORM, t4) : 1.f;
        float on = fminf(t4, MAXNORM);
        float tl = __fdividef(artanh_fast(on), on);   // final logmap0 scale
        float oc = t4 * inv4 * fo * tl;
#pragma unroll
        for (int j = 0; j < 5; j++) myslab[r * 168 + j * 33 + lane] = oc * xt[j];
    }
    __syncwarp();

    // ---- attention: lane -> (hh = lane/5, kk = lane%5) ----
    float* attw = attws + wid * 32;
    const int hh = lane / 5, kk = lane - hh * 5;
    float a_un = 0.f;
    if (lane < 25) {
        const float* ag = myslab + 5 * 168 + hh * 33;
        const float* ng = myslab + kk * 168 + hh * 33;
        float s = 0.f;
#pragma unroll
        for (int d = 0; d < 32; d++) s = fmaf(ag[d], ng[d], s);
        a_un = s;
    }
    attw[lane] = a_un;
    __syncwarp();
    float aval = 0.f;
    if (lane < 25) {
        float m = -3.4e38f;
#pragma unroll
        for (int k2 = 0; k2 < 5; k2++) m = fmaxf(m, attw[hh * 5 + k2]);
        float se = 0.f;
#pragma unroll
        for (int k2 = 0; k2 < 5; k2++) se += __expf(attw[hh * 5 + k2] - m);
        aval = __expf(a_un - m) * __fdividef(1.f, se);
        attr[(size_t)bid * 25 + lane] = aval;
    }
    attw[lane] = aval;
    __syncwarp();

    // out[d=lane] = 0.2 * sum_{h,k} att[h][k] * neigh[k][h][d]
    float o = 0.f;
#pragma unroll
    for (int h2 = 0; h2 < 5; h2++)
#pragma unroll
        for (int k2 = 0; k2 < 5; k2++)
            o = fmaf(attw[h2 * 5 + k2], myslab[k2 * 168 + h2 * 33 + lane], o);
    o *= 0.2f;

    // ---- final W2 layer (J = 1) ----
    {
        const float hb2l = hb2[lane];
        const float hbn2b = hbn[1];
        float n, inv;
        norm_inv(wredsum(o * o), n, inv);
        float t = tanh_fast(n);
        float f = (t > MAXNORM) ? __fdividef(MAXNORM, t) : 1.f;
        float pp = t * inv * o * f;
        float ppn = fminf(t, MAXNORM);
        float mxv = 0.f;
#pragma unroll
        for (int d = 0; d < 32; d++) {
            float pd = __shfl_sync(FULLM, pp, d);
            mxv = fmaf(w2t[d * 33 + lane], pd, mxv);
        }
        float mxn, inv2;
        norm_inv(wredsum(mxv * mxv), mxn, inv2);
        float arg = mxn * __fdividef(artanh_fast(ppn), ppn);
        float t2 = tanh_fast(arg);
        float zf = __ballot_sync(FULLM, mxv != 0.f) ? 1.f : 0.f;
        float rn = zf * t2;
        float fpr = (rn > MAXNORM) ? __fdividef(MAXNORM, rn) : 1.f;
        float res = zf * t2 * inv2 * fpr * mxv;
        float rp = fminf(rn, MAXNORM);
        float x2 = rp * rp;
        float xy = wredsum(res * hb2l);
        float num_a = 1.f + 2.f * xy + hbn2b;
        float num_b = 1.f - x2;
        float rden = __fdividef(1.f, fmaxf(1.f + 2.f * xy + x2 * hbn2b, MINN));
        float h = (num_a * res + num_b * hb2l) * rden;
        float hn, inv3;
        norm_inv(wredsum(h * h), hn, inv3);
        float fh = (hn > MAXNORM) ? __fdividef(MAXNORM, hn) : 1.f;
        hn = fminf(hn, MAXNORM);
        float th = __fdividef(artanh_fast(hn), hn) * fh;
        float xt = fmaxf(th * h, 0.f);
        float tn, inv4;
        norm_inv(wredsum(xt * xt), tn, inv4);
        float t4 = tanh_fast(tn);
        float fo = (t4 > MAXNORM) ? __fdividef(MAXNORM, t4) : 1.f;
        outp[(size_t)bid * 32 + lane] = t4 * inv4 * fo * xt;
    }
}

extern "C" void kernel_launch(void* const* d_in, const int* in_sizes, int n_in,
                              void* d_out, int out_size) {
    const float* in_feats = (const float*)d_in[0];
    const float* in_nei   = (const float*)d_in[1];
    const float* W1       = (const float*)d_in[2];
    const float* b1       = (const float*)d_in[3];
    const float* W2       = (const float*)d_in[4];
    const float* b2       = (const float*)d_in[5];
    float* outp = (float*)d_out;
    float* attr = outp + 4 * 1024 * 32;   // out first, att_record second

    const int smem_bytes = (5152 + 1056 + 160 + 32 + 2 + 8 * 1008 + 8 * 32) * 4;
    cudaFuncSetAttribute(k_bidpipe, cudaFuncAttributeMaxDynamicSharedMemorySize, smem_bytes);

    k_gather<<<3072, 256>>>(in_nei, in_feats);
    k_bidpipe<<<512, 256, smem_bytes>>>(W1, b1, W2, b2, outp, attr);
}

// round 6
// speedup vs baseline: 3.9399x; 1.1545x over previous
#include <cuda_runtime.h>
#include <math.h>

#define FULLM 0xffffffffu
#define MINN 1e-15f
#define MAXNORM 0.996f        // (1 - 0.004) / sqrt(c), c = 1
#define ATANH_MAX 3.1063030f  // artanh(0.996)
#define ATANH_MAX2 9.6491187f // artanh(0.996)^2

// ---------------- device scratch ----------------
__device__ float g_p[24576 * 32];   // ball-mapped rows (3.1MB, L2-resident)
__device__ float g_lam[24576];      // artanh(|p|)/|p| per row

// ---------------- helpers ----------------
__device__ __forceinline__ float wredsum(float v) {
#pragma unroll
    for (int o = 16; o; o >>= 1) v += __shfl_xor_sync(FULLM, v, o);
    return v;
}
__device__ __forceinline__ void wredsum2(float& a, float& b) {
#pragma unroll
    for (int o = 16; o; o >>= 1) {
        a += __shfl_xor_sync(FULLM, a, o);
        b += __shfl_xor_sync(FULLM, b, o);
    }
}
__device__ __forceinline__ float tanh_fast(float x) {   // x >= 0, clip 15
    x = fminf(x, 15.f);
    float e = __expf(-2.f * x);
    return __fdividef(1.f - e, 1.f + e);
}
__device__ __forceinline__ float artanh_fast(float x) {
    x = fminf(fmaxf(x, -1.f + 1e-7f), 1.f - 1e-7f);
    return 0.5f * __logf(__fdividef(1.f + x, 1.f - x));
}
__device__ __forceinline__ void norm_inv(float s, float& n, float& inv) {
    s = fmaxf(s, 1e-30f);
    inv = __frsqrt_rn(s);
    n = s * inv;
}

// hyp bias proj(expmap0(b)); warp-collective, writes smem
template <int J>
__device__ __forceinline__ void make_hyp_bias(const float* b, float* hb, float* hbn2) {
    const int lane = threadIdx.x & 31;
    float v[J];
    float s = 0.f;
#pragma unroll
    for (int j = 0; j < J; j++) { v[j] = b[lane * J + j]; s += v[j] * v[j]; }
    float n, inv;
    norm_inv(wredsum(s), n, inv);
    float t = tanh_fast(n);
#pragma unroll
    for (int j = 0; j < J; j++) v[j] *= t * inv;
    float f = (t > MAXNORM) ? __fdividef(MAXNORM, t) : 1.f;
    float vn = fminf(t, MAXNORM);
#pragma unroll
    for (int j = 0; j < J; j++) hb[lane * J + j] = v[j] * f;
    if (lane == 0) *hbn2 = vn * vn;
}

// ---------------- kernel 1: gather + logmap0 + expmap0 + proj ----------------
// tasks t in [0, 24576): bid = t/6, k = t%6 (k==5 -> agent row). One warp/task.
__global__ void __launch_bounds__(256) k_gather(const float* __restrict__ in_nei,
                                                const float* __restrict__ in_feats) {
    const int tid = threadIdx.x, wid = tid >> 5, lane = tid & 31;
    const int t = blockIdx.x * 8 + wid;
    const int bid = t / 6;
    const int k = t - bid * 6;
    const float* fbase = in_feats + (bid >> 10) * (1024 * 32);

    float x = 0.f;
    if (k == 5) {
        float f = in_feats[bid * 32 + lane];
        float n, inv;
        norm_inv(wredsum(f * f), n, inv);
        x = __fdividef(artanh_fast(n), n) * f;
    } else {
        const float4* p4 = (const float4*)(in_nei + ((size_t)bid * 5 + k) * 1024);
        auto addc = [&](float w, int n) {
            if (w != 0.f) {   // warp-uniform (w broadcast)
                float f = fbase[n * 32 + lane];
                float nn, inv;
                norm_inv(wredsum(f * f), nn, inv);
                x = fmaf(w * __fdividef(artanh_fast(nn), nn), f, x);
            }
        };
#pragma unroll 1
        for (int pr = 0; pr < 4; pr++) {
            float4 a = p4[pr * 64 + lane];
            float4 b = p4[pr * 64 + 32 + lane];
            bool nz = (a.x != 0.f) || (a.y != 0.f) || (a.z != 0.f) || (a.w != 0.f) ||
                      (b.x != 0.f) || (b.y != 0.f) || (b.z != 0.f) || (b.w != 0.f);
            unsigned mk = __ballot_sync(FULLM, nz);
            if (mk) {
                while (mk) {
                    int src = __ffs(mk) - 1;
                    mk &= mk - 1u;
                    float ax = __shfl_sync(FULLM, a.x, src), ay = __shfl_sync(FULLM, a.y, src);
                    float az = __shfl_sync(FULLM, a.z, src), aw = __shfl_sync(FULLM, a.w, src);
                    float bx = __shfl_sync(FULLM, b.x, src), by = __shfl_sync(FULLM, b.y, src);
                    float bz = __shfl_sync(FULLM, b.z, src), bw = __shfl_sync(FULLM, b.w, src);
                    int na = pr * 256 + src * 4;
                    int nb = pr * 256 + 128 + src * 4;
                    addc(ax, na + 0); addc(ay, na + 1); addc(az, na + 2); addc(aw, na + 3);
                    addc(bx, nb + 0); addc(by, nb + 1); addc(bz, nb + 2); addc(bw, nb + 3);
                }
                break;   // one-hot row: first nonzero pair is the only one
            }
        }
    }
    // expmap0 + proj on the fly (latency-bound kernel: ALU is free)
    float n, inv;
    norm_inv(wredsum(x * x), n, inv);
    float tt = tanh_fast(n);
    float f = (tt > MAXNORM) ? __fdividef(MAXNORM, tt) : 1.f;
    float pnr = fminf(tt, MAXNORM);
    g_p[(size_t)t * 32 + lane] = tt * inv * f * x;
    if (lane == 0)
        g_lam[t] = (pnr > 1e-6f) ? __fdividef(artanh_fast(pnr), pnr) : 1.f;
}

// ---------------- kernel 2: per-bid pipeline (heads + attention + W2) ----------------
// 8 warps/block, 2 bids/warp, grid = 256 (single wave at 3 blocks/SM).
__global__ void __launch_bounds__(256, 3) k_bidpipe(const float* __restrict__ W1,
                                                    const float* __restrict__ b1,
                                                    const float* __restrict__ W2,
                                                    const float* __restrict__ b2,
                                                    float* __restrict__ outp,
                                                    float* __restrict__ attr) {
    extern __shared__ float sm[];
    float* w1t = sm;                    // 32*161  [d*161 + m]
    float* w2t = w1t + 5152;            // 32*33   [d*33 + m]
    float* hb1 = w2t + 1056;            // 160
    float* hb2 = hb1 + 160;             // 32
    float* hbn = hb2 + 32;              // 2
    float* slab = hbn + 2;              // 8 * 1008  [wid][r*168 + j*33 + d]
    float* attws = slab + 8 * 1008;     // 8 * 32

    const int tid = threadIdx.x, wid = tid >> 5, lane = tid & 31;

    if (wid == 0) {
        make_hyp_bias<5>(b1, hb1, &hbn[0]);
    } else if (wid == 1) {
        make_hyp_bias<1>(b2, hb2, &hbn[1]);
    } else {
        for (int i = tid - 64; i < 6208; i += 192) {
            if (i < 5152) {
                int m = i >> 5, d = i & 31;
                w1t[d * 161 + m] = W1[i];
            } else {
                int j = i - 5152;
                int m = j >> 5, d = j & 31;
                w2t[d * 33 + m] = W2[j];
            }
        }
    }
    __syncthreads();

    const float hbn2 = hbn[0];
    float* myslab = slab + wid * 1008;
    float* attw = attws + wid * 32;
    float hbl[5];
#pragma unroll
    for (int j = 0; j < 5; j++) hbl[j] = hb1[lane * 5 + j];

#pragma unroll 1
    for (int rep = 0; rep < 2; rep++) {
        const int bid = (blockIdx.x * 8 + wid) * 2 + rep;

        // ---- load 6 ball points + lambdas ----
        float p[6], lam[6];
#pragma unroll
        for (int r = 0; r < 6; r++) {
            p[r] = g_p[(size_t)(bid * 6 + r) * 32 + lane];
            lam[r] = g_lam[bid * 6 + r];
        }
        // ---- batched matvec: mx[r][j] = sum_d W1[lane*5+j][d] * p[r][d] ----
        float mx[6][5];
#pragma unroll
        for (int r = 0; r < 6; r++)
#pragma unroll
            for (int j = 0; j < 5; j++) mx[r][j] = 0.f;
#pragma unroll
        for (int d = 0; d < 32; d++) {
            float w0 = w1t[d * 161 + lane * 5 + 0];
            float w1 = w1t[d * 161 + lane * 5 + 1];
            float w2 = w1t[d * 161 + lane * 5 + 2];
            float w3 = w1t[d * 161 + lane * 5 + 3];
            float w4 = w1t[d * 161 + lane * 5 + 4];
#pragma unroll
            for (int r = 0; r < 6; r++) {
                float pd = __shfl_sync(FULLM, p[r], d);
                mx[r][0] = fmaf(w0, pd, mx[r][0]);
                mx[r][1] = fmaf(w1, pd, mx[r][1]);
                mx[r][2] = fmaf(w2, pd, mx[r][2]);
                mx[r][3] = fmaf(w3, pd, mx[r][3]);
                mx[r][4] = fmaf(w4, pd, mx[r][4]);
            }
        }
        // ---- per-row epilogue (2 reduction rounds, 2 transcendentals) ----
#pragma unroll
        for (int r = 0; r < 6; r++) {
            float s2 = 0.f, q = 0.f;
#pragma unroll
            for (int j = 0; j < 5; j++) {
                s2 = fmaf(mx[r][j], mx[r][j], s2);
                q = fmaf(mx[r][j], hbl[j], q);
            }
            wredsum2(s2, q);                       // dual interleaved butterfly
            float mxn, inv2;
            norm_inv(s2, mxn, inv2);
            float t2 = tanh_fast(mxn * lam[r]);
            bool lz = (mx[r][0] != 0.f) || (mx[r][1] != 0.f) || (mx[r][2] != 0.f) ||
                      (mx[r][3] != 0.f) || (mx[r][4] != 0.f);
            float zf = __ballot_sync(FULLM, lz) ? 1.f : 0.f;
            float rn = zf * t2;
            float fpr = (rn > MAXNORM) ? __fdividef(MAXNORM, rn) : 1.f;
            float sc = zf * t2 * inv2 * fpr;       // res = sc * mx
            float xy = sc * q;                     // <res, hb>
            float rp = fminf(rn, MAXNORM);
            float x2 = rp * rp;                    // |res|^2 analytic
            float num_a = 1.f + 2.f * xy + hbn2;
            float num_b = 1.f - x2;
            float rden = __fdividef(1.f, fmaxf(1.f + 2.f * xy + x2 * hbn2, MINN));
            // |h|^2 analytic
            float s3 = rden * rden *
                       (num_a * num_a * x2 + 2.f * num_a * num_b * xy + num_b * num_b * hbn2);
            float hn = sqrtf(s3);
            float th = (hn > 1e-6f)
                           ? __fdividef(artanh_fast(fminf(hn, MAXNORM)), hn)
                           : 1.f;                  // proj + logmap0 combined
            float xt[5];
            float s4 = 0.f;
#pragma unroll
            for (int j = 0; j < 5; j++) {
                float h = (num_a * sc * mx[r][j] + num_b * hbl[j]) * rden;
                xt[j] = fmaxf(th * h, 0.f);
                s4 = fmaf(xt[j], xt[j], s4);
            }
            s4 = wredsum(s4);
            // logmap0(proj(expmap0(xt))) = xt unless |expmap0(xt)| > MAXNORM
            float oc = (s4 > ATANH_MAX2) ? ATANH_MAX * __frsqrt_rn(s4) : 1.f;
#pragma unroll
            for (int j = 0; j < 5; j++) myslab[r * 168 + j * 33 + lane] = oc * xt[j];
        }
        __syncwarp();

        // ---- attention: lane -> (hh = lane/5, kk = lane%5) ----
        const int hh = lane / 5, kk = lane - hh * 5;
        float a_un = 0.f;
        if (lane < 25) {
            const float* ag = myslab + 5 * 168 + hh * 33;
            const float* ng = myslab + kk * 168 + hh * 33;
            float s = 0.f;
#pragma unroll
            for (int d = 0; d < 32; d++) s = fmaf(ag[d], ng[d], s);
            a_un = s;
        }
        attw[lane] = a_un;
        __syncwarp();
        float aval = 0.f;
        if (lane < 25) {
            float m = -3.4e38f;
#pragma unroll
            for (int k2 = 0; k2 < 5; k2++) m = fmaxf(m, attw[hh * 5 + k2]);
            float se = 0.f;
#pragma unroll
            for (int k2 = 0; k2 < 5; k2++) se += __expf(attw[hh * 5 + k2] - m);
            aval = __expf(a_un - m) * __fdividef(1.f, se);
            attr[(size_t)bid * 25 + lane] = aval;
        }
        attw[lane] = aval;
        __syncwarp();

        float o = 0.f;
#pragma unroll
        for (int h2 = 0; h2 < 5; h2++)
#pragma unroll
            for (int k2 = 0; k2 < 5; k2++)
                o = fmaf(attw[h2 * 5 + k2], myslab[k2 * 168 + h2 * 33 + lane], o);
        o *= 0.2f;

        // ---- final W2 layer (ends with expmap0+proj; no collapse) ----
        {
            const float hb2l = hb2[lane];
            const float hbn2b = hbn[1];
            float n, inv;
            norm_inv(wredsum(o * o), n, inv);
            float t = tanh_fast(n);
            float f = (t > MAXNORM) ? __fdividef(MAXNORM, t) : 1.f;
            float pp = t * inv * o * f;
            float ppn = fminf(t, MAXNORM);
            float lamb = (ppn > 1e-6f) ? __fdividef(artanh_fast(ppn), ppn) : 1.f;
            float mxv = 0.f;
#pragma unroll
            for (int d = 0; d < 32; d++) {
                float pd = __shfl_sync(FULLM, pp, d);
                mxv = fmaf(w2t[d * 33 + lane], pd, mxv);
            }
            float s2 = mxv * mxv, q = mxv * hb2l;
            wredsum2(s2, q);
            float mxn, inv2;
            norm_inv(s2, mxn, inv2);
            float t2 = tanh_fast(mxn * lamb);
            float zf = __ballot_sync(FULLM, mxv != 0.f) ? 1.f : 0.f;
            float rn = zf * t2;
            float fpr = (rn > MAXNORM) ? __fdividef(MAXNORM, rn) : 1.f;
            float sc = zf * t2 * inv2 * fpr;
            float xy = sc * q;
            float rp = fminf(rn, MAXNORM);
            float x2 = rp * rp;
            float num_a = 1.f + 2.f * xy + hbn2b;
            float num_b = 1.f - x2;
            float rden = __fdividef(1.f, fmaxf(1.f + 2.f * xy + x2 * hbn2b, MINN));
            float s3 = rden * rden *
                       (num_a * num_a * x2 + 2.f * num_a * num_b * xy + num_b * num_b * hbn2b);
            float hn = sqrtf(s3);
            float th = (hn > 1e-6f)
                           ? __fdividef(artanh_fast(fminf(hn, MAXNORM)), hn)
                           : 1.f;
            float h = (num_a * sc * mxv + num_b * hb2l) * rden;
            float xt = fmaxf(th * h, 0.f);
            float tn, inv4;
            norm_inv(wredsum(xt * xt), tn, inv4);
            float t4 = tanh_fast(tn);
            float fo = (t4 > MAXNORM) ? __fdividef(MAXNORM, t4) : 1.f;
            outp[(size_t)bid * 32 + lane] = t4 * inv4 * fo * xt;
        }
        __syncwarp();
    }
}

extern "C" void kernel_launch(void* const* d_in, const int* in_sizes, int n_in,
                              void* d_out, int out_size) {
    const float* in_feats = (const float*)d_in[0];
    const float* in_nei   = (const float*)d_in[1];
    const float* W1       = (const float*)d_in[2];
    const float* b1       = (const float*)d_in[3];
    const float* W2       = (const float*)d_in[4];
    const float* b2       = (const float*)d_in[5];
    float* outp = (float*)d_out;
    float* attr = outp + 4 * 1024 * 32;   // out first, att_record second

    const int smem_bytes = (5152 + 1056 + 160 + 32 + 2 + 8 * 1008 + 8 * 32) * 4;
    cudaFuncSetAttribute(k_bidpipe, cudaFuncAttributeMaxDynamicSharedMemorySize, smem_bytes);

    k_gather<<<3072, 256>>>(in_nei, in_feats);
    k_bidpipe<<<256, 256, smem_bytes>>>(W1, b1, W2, b2, outp, attr);
}